// round 3
// baseline (speedup 1.0000x reference)
#include <cuda_runtime.h>
#include <math.h>

// ---------------------------------------------------------------------------
// Problem constants
// ---------------------------------------------------------------------------
#define NPATCH 1800            // B(8) * L(225)
#define NTOK   64              // k*k
#define CDIM   256
#define QKVDIM 768
#define MROWS  (NPATCH * NTOK) // 115200

// ---------------------------------------------------------------------------
// Global scratch (device mallocs are forbidden; __device__ arrays are the
// sanctioned workaround). Buffers are aliased across pipeline stages to
// minimize the static footprint:
//   g_big  : qkv (stage 2 out, stage 3 in)  then  y (stage 4 out, stage 5 in)
//   g_mid  : h   (stage 1 out, stage 2 in)  then  o (stage 3 out, stage 4 in)
// Liveness check: h is dead once qkv exists; qkv is dead once o exists.
// ---------------------------------------------------------------------------
__device__ float g_big[NPATCH * NTOK * QKVDIM];  // 354 MB
__device__ float g_mid[NPATCH * NTOK * CDIM];    // 118 MB

// ---------------------------------------------------------------------------
// Utilities
// ---------------------------------------------------------------------------
__device__ __forceinline__ float warp_sum(float v) {
#pragma unroll
    for (int o = 16; o; o >>= 1) v += __shfl_xor_sync(0xffffffffu, v, o);
    return v;
}

// ---------------------------------------------------------------------------
// Kernel 1: gather patches + LayerNorm x2
// One warp per (patch, token) row of 256 channels. Block = 8 warps.
// ---------------------------------------------------------------------------
__global__ __launch_bounds__(256) void k_gather_ln(
    const float* __restrict__ x,
    const float* __restrict__ g1, const float* __restrict__ b1,
    const float* __restrict__ g2, const float* __restrict__ b2,
    float* __restrict__ hout)
{
    int warp = threadIdx.x >> 5, lane = threadIdx.x & 31;
    int row = blockIdx.x * 8 + warp;          // 0..115199
    int p = row >> 6, t = row & 63;
    int b = p / 225, l = p - b * 225;
    int ph = l / 15, pw = l - ph * 15;
    int gr = ph * 4 + (t >> 3);
    int gc = pw * 4 + (t & 7);
    const float* xr = x + (((size_t)(b * 64 + gr)) * 64 + gc) * 256;

    float v[8];
    float s = 0.f;
#pragma unroll
    for (int i = 0; i < 8; i++) { v[i] = xr[lane + i * 32]; s += v[i]; }
    s = warp_sum(s);
    float mean = s * (1.f / 256.f);
    float vs = 0.f;
#pragma unroll
    for (int i = 0; i < 8; i++) { v[i] -= mean; vs += v[i] * v[i]; }
    vs = warp_sum(vs);
    float inv = rsqrtf(vs * (1.f / 256.f) + 1e-5f);

    float s2 = 0.f;
#pragma unroll
    for (int i = 0; i < 8; i++) {
        v[i] = v[i] * inv * g1[lane + i * 32] + b1[lane + i * 32];
        s2 += v[i];
    }
    s2 = warp_sum(s2);
    float mean2 = s2 * (1.f / 256.f);
    float vs2 = 0.f;
#pragma unroll
    for (int i = 0; i < 8; i++) { v[i] -= mean2; vs2 += v[i] * v[i]; }
    vs2 = warp_sum(vs2);
    float inv2 = rsqrtf(vs2 * (1.f / 256.f) + 1e-5f);

    float* hr = hout + (size_t)row * 256;
#pragma unroll
    for (int i = 0; i < 8; i++)
        hr[lane + i * 32] = v[i] * inv2 * g2[lane + i * 32] + b2[lane + i * 32];
}

// ---------------------------------------------------------------------------
// Kernel 2/4: fp32 SGEMM  C[M,N] = A[M,K] @ B[K,N] (+ bias)
// 128x128 block tile, BK=16, 8x8 per-thread microtile, 256 threads.
// M % 128 == 0, N % 128 == 0, K % 16 == 0 (holds for all our shapes).
// ---------------------------------------------------------------------------
#define BMg 128
#define BNg 128
#define BKg 16
#define TMg 8
#define TNg 8

__global__ __launch_bounds__(256) void k_sgemm(
    const float* __restrict__ A, const float* __restrict__ B,
    const float* __restrict__ bias, float* __restrict__ C,
    int M, int N, int K)
{
    __shared__ float As[BKg][BMg + 4];   // transposed A tile
    __shared__ float Bs[BKg][BNg + 4];

    int tid = threadIdx.x;
    int bn = blockIdx.x * BNg;
    int bm = blockIdx.y * BMg;
    int tx = tid & 15, ty = tid >> 4;

    float acc[TMg][TNg];
#pragma unroll
    for (int i = 0; i < TMg; i++)
#pragma unroll
        for (int j = 0; j < TNg; j++) acc[i][j] = 0.f;

    for (int k0 = 0; k0 < K; k0 += BKg) {
        // Load A tile (BM x BK) transposed into As[k][m]
#pragma unroll
        for (int i = 0; i < 2; i++) {
            int vv = tid + i * 256;           // 0..511
            int m  = vv >> 2;                 // 0..127
            int kv = (vv & 3) * 4;            // 0,4,8,12
            float4 a4 = *(const float4*)(A + (size_t)(bm + m) * K + k0 + kv);
            As[kv + 0][m] = a4.x; As[kv + 1][m] = a4.y;
            As[kv + 2][m] = a4.z; As[kv + 3][m] = a4.w;
        }
        // Load B tile (BK x BN)
#pragma unroll
        for (int i = 0; i < 2; i++) {
            int vv = tid + i * 256;           // 0..511
            int r  = vv >> 5;                 // 0..15
            int cv = (vv & 31) * 4;           // 0..124
            *(float4*)&Bs[r][cv] = *(const float4*)(B + (size_t)(k0 + r) * N + bn + cv);
        }
        __syncthreads();

#pragma unroll
        for (int kk = 0; kk < BKg; kk++) {
            float a[TMg], bb[TNg];
            float4 t0 = *(const float4*)&As[kk][ty * TMg];
            float4 t1 = *(const float4*)&As[kk][ty * TMg + 4];
            a[0] = t0.x; a[1] = t0.y; a[2] = t0.z; a[3] = t0.w;
            a[4] = t1.x; a[5] = t1.y; a[6] = t1.z; a[7] = t1.w;
            float4 u0 = *(const float4*)&Bs[kk][tx * TNg];
            float4 u1 = *(const float4*)&Bs[kk][tx * TNg + 4];
            bb[0] = u0.x; bb[1] = u0.y; bb[2] = u0.z; bb[3] = u0.w;
            bb[4] = u1.x; bb[5] = u1.y; bb[6] = u1.z; bb[7] = u1.w;
#pragma unroll
            for (int i = 0; i < TMg; i++)
#pragma unroll
                for (int j = 0; j < TNg; j++) acc[i][j] += a[i] * bb[j];
        }
        __syncthreads();
    }

    // Epilogue (+ optional bias)
#pragma unroll
    for (int i = 0; i < TMg; i++) {
        size_t roff = (size_t)(bm + ty * TMg + i) * N + bn + tx * TNg;
#pragma unroll
        for (int j = 0; j < TNg; j += 4) {
            float4 r4;
            if (bias) {
                const float4 bi = *(const float4*)(bias + bn + tx * TNg + j);
                r4.x = acc[i][j + 0] + bi.x;
                r4.y = acc[i][j + 1] + bi.y;
                r4.z = acc[i][j + 2] + bi.z;
                r4.w = acc[i][j + 3] + bi.w;
            } else {
                r4.x = acc[i][j + 0]; r4.y = acc[i][j + 1];
                r4.z = acc[i][j + 2]; r4.w = acc[i][j + 3];
            }
            *(float4*)(C + roff + j) = r4;
        }
    }
}

// ---------------------------------------------------------------------------
// Kernel 3: per-patch multi-head attention (online softmax).
// One CTA per patch, 512 threads = (head, query token).
// Q/K/V staged in smem with row stride 260 (pad for bank conflicts, keeps
// float4 alignment for the broadcast K/V reads).
// ---------------------------------------------------------------------------
#define ATTN_STRIDE 260
#define ATTN_SMEM   (3 * 64 * ATTN_STRIDE * 4)

__global__ __launch_bounds__(512) void k_attn(
    const float* __restrict__ qkv, float* __restrict__ oout)
{
    extern __shared__ float sm[];
    float* Qs = sm;
    float* Ks = sm + 64 * ATTN_STRIDE;
    float* Vs = sm + 2 * 64 * ATTN_STRIDE;

    int p = blockIdx.x;
    int tid = threadIdx.x;
    const float* src = qkv + (size_t)p * 64 * 768;

    // Coalesced load of the patch's qkv into padded smem
    for (int idx = tid; idx < 64 * 768; idx += 512) {
        int row = idx / 768;
        int col = idx - row * 768;
        int sec = col >> 8;          // 0=q 1=k 2=v
        int cc  = col & 255;
        sm[sec * (64 * ATTN_STRIDE) + row * ATTN_STRIDE + cc] = src[idx];
    }
    __syncthreads();

    int h = tid >> 6, t = tid & 63;
    const int hb = h * 32;

    float q[32];
    {
        const float* qr = Qs + t * ATTN_STRIDE + hb;
#pragma unroll
        for (int d = 0; d < 32; d++)
            q[d] = qr[d] * 0.17677669529663687f;   // 1/sqrt(32)
    }

    float m = -1e30f, ssum = 0.f;
    float o[32];
#pragma unroll
    for (int d = 0; d < 32; d++) o[d] = 0.f;

    for (int j = 0; j < 64; j++) {
        const float4* kr = (const float4*)(Ks + j * ATTN_STRIDE + hb);
        float s = 0.f;
#pragma unroll
        for (int d4 = 0; d4 < 8; d4++) {
            float4 k4 = kr[d4];
            s += q[d4 * 4 + 0] * k4.x + q[d4 * 4 + 1] * k4.y
               + q[d4 * 4 + 2] * k4.z + q[d4 * 4 + 3] * k4.w;
        }
        float mn   = fmaxf(m, s);
        float corr = __expf(m - mn);
        float e    = __expf(s - mn);
        ssum = ssum * corr + e;
        const float4* vr = (const float4*)(Vs + j * ATTN_STRIDE + hb);
#pragma unroll
        for (int d4 = 0; d4 < 8; d4++) {
            float4 v4 = vr[d4];
            o[d4 * 4 + 0] = o[d4 * 4 + 0] * corr + e * v4.x;
            o[d4 * 4 + 1] = o[d4 * 4 + 1] * corr + e * v4.y;
            o[d4 * 4 + 2] = o[d4 * 4 + 2] * corr + e * v4.z;
            o[d4 * 4 + 3] = o[d4 * 4 + 3] * corr + e * v4.w;
        }
        m = mn;
    }

    float invs = 1.f / ssum;
    __syncthreads();   // done reading Qs, safe to overwrite
    {
        float* qr = Qs + t * ATTN_STRIDE + hb;
#pragma unroll
        for (int d = 0; d < 32; d++) qr[d] = o[d] * invs;
    }
    __syncthreads();

    float* dst = oout + (size_t)p * 64 * 256;
    for (int idx = tid; idx < 64 * 256; idx += 512) {
        int row = idx >> 8, cc = idx & 255;
        dst[idx] = Qs[row * ATTN_STRIDE + cc];
    }
}

// ---------------------------------------------------------------------------
// Kernel 5: deterministic overlap-gather + count normalization.
// One CTA (256 threads = channels) per output pixel.
// ---------------------------------------------------------------------------
__global__ __launch_bounds__(256) void k_scatter(
    const float* __restrict__ y, float* __restrict__ out)
{
    int pix = blockIdx.x;                 // 0..32767
    int ch  = threadIdx.x;
    int b = pix >> 12;
    int r = (pix >> 6) & 63;
    int c = pix & 63;

    int ph_lo = max(0, (r - 4) >> 2);     // floor((r-7+3)/4), clamped
    int ph_hi = min(14, r >> 2);
    int pw_lo = max(0, (c - 4) >> 2);
    int pw_hi = min(14, c >> 2);

    float acc = 0.f;
    for (int ph = ph_lo; ph <= ph_hi; ph++) {
        for (int pw = pw_lo; pw <= pw_hi; pw++) {
            int p = b * 225 + ph * 15 + pw;
            int t = (r - ph * 4) * 8 + (c - pw * 4);
            acc += y[((size_t)p * 64 + t) * 256 + ch];
        }
    }
    float cnt = (float)((ph_hi - ph_lo + 1) * (pw_hi - pw_lo + 1));
    out[(size_t)pix * 256 + ch] = acc * (1.f / cnt);
}

// ---------------------------------------------------------------------------
// Entry point
// ---------------------------------------------------------------------------
extern "C" void kernel_launch(void* const* d_in, const int* in_sizes, int n_in,
                              void* d_out, int out_size)
{
    const float* x    = (const float*)d_in[0];
    const float* g1   = (const float*)d_in[1];
    const float* b1   = (const float*)d_in[2];
    const float* g2   = (const float*)d_in[3];
    const float* b2   = (const float*)d_in[4];
    const float* wqkv = (const float*)d_in[5];
    const float* wout = (const float*)d_in[6];
    const float* bout = (const float*)d_in[7];
    float* out = (float*)d_out;

    float *bigbuf, *midbuf;
    cudaGetSymbolAddress((void**)&bigbuf, g_big);
    cudaGetSymbolAddress((void**)&midbuf, g_mid);

    // Aliased views (see liveness note at the buffer definitions)
    float* hbuf   = midbuf;   // stage 1 out / stage 2 in
    float* qkvbuf = bigbuf;   // stage 2 out / stage 3 in
    float* obuf   = midbuf;   // stage 3 out / stage 4 in (h is dead)
    float* ybuf   = bigbuf;   // stage 4 out / stage 5 in (qkv is dead)

    cudaFuncSetAttribute(k_attn, cudaFuncAttributeMaxDynamicSharedMemorySize, ATTN_SMEM);

    k_gather_ln<<<MROWS / 8, 256>>>(x, g1, b1, g2, b2, hbuf);
    k_sgemm<<<dim3(QKVDIM / BNg, MROWS / BMg), 256>>>(hbuf, wqkv, nullptr, qkvbuf,
                                                      MROWS, QKVDIM, CDIM);
    k_attn<<<NPATCH, 512, ATTN_SMEM>>>(qkvbuf, obuf);
    k_sgemm<<<dim3(CDIM / BNg, MROWS / BMg), 256>>>(obuf, wout, bout, ybuf,
                                                    MROWS, CDIM, CDIM);
    k_scatter<<<8 * 64 * 64, 256>>>(ybuf, out);
}

// round 5
// speedup vs baseline: 1.6180x; 1.6180x over previous
#include <cuda_runtime.h>
#include <cuda_bf16.h>
#include <cstdint>
#include <math.h>

// ---------------------------------------------------------------------------
// Problem constants
// ---------------------------------------------------------------------------
#define NPATCH 1800            // B(8) * L(225)
#define NTOK   64              // k*k
#define CDIM   256
#define QKVDIM 768
#define MROWS  (NPATCH * NTOK) // 115200

// ---------------------------------------------------------------------------
// Global scratch. Aliasing:
//   g_big : qkv fp32 (GEMM1 out / attn in) then y fp32 (GEMM2 out / scatter in)
//   g_phi/g_plo : h hi/lo planes (LN out / GEMM1 A) then o hi/lo (attn out / GEMM2 A)
// ---------------------------------------------------------------------------
__device__ float          g_big[(size_t)MROWS * QKVDIM];   // 354 MB
__device__ __nv_bfloat16  g_phi[(size_t)MROWS * CDIM];     // 59 MB
__device__ __nv_bfloat16  g_plo[(size_t)MROWS * CDIM];     // 59 MB
__device__ __nv_bfloat16  g_wqT_hi[QKVDIM * CDIM];
__device__ __nv_bfloat16  g_wqT_lo[QKVDIM * CDIM];
__device__ __nv_bfloat16  g_woT_hi[CDIM * CDIM];
__device__ __nv_bfloat16  g_woT_lo[CDIM * CDIM];

// ---------------------------------------------------------------------------
// Helpers
// ---------------------------------------------------------------------------
__device__ __forceinline__ uint32_t smem_to_u32(const void* p) {
    uint32_t a;
    asm("{ .reg .u64 t; cvta.to.shared.u64 t, %1; cvt.u32.u64 %0, t; }"
        : "=r"(a) : "l"(p));
    return a;
}
__device__ __forceinline__ float warp_sum(float v) {
#pragma unroll
    for (int o = 16; o; o >>= 1) v += __shfl_xor_sync(0xffffffffu, v, o);
    return v;
}
__device__ __forceinline__ void split_bf16(float v, __nv_bfloat16& hi, __nv_bfloat16& lo) {
    hi = __float2bfloat16(v);
    lo = __float2bfloat16(v - __bfloat162float(hi));
}
__device__ __forceinline__ void ldsm_x4(uint32_t addr, uint32_t& r0, uint32_t& r1,
                                        uint32_t& r2, uint32_t& r3) {
    asm volatile("ldmatrix.sync.aligned.m8n8.x4.shared.b16 {%0,%1,%2,%3}, [%4];"
                 : "=r"(r0), "=r"(r1), "=r"(r2), "=r"(r3) : "r"(addr));
}
__device__ __forceinline__ void mma_bf16(float* d, const uint32_t* a,
                                         uint32_t b0, uint32_t b1) {
    asm volatile(
        "mma.sync.aligned.m16n8k16.row.col.f32.bf16.bf16.f32 "
        "{%0,%1,%2,%3}, {%4,%5,%6,%7}, {%8,%9}, {%0,%1,%2,%3};"
        : "+f"(d[0]), "+f"(d[1]), "+f"(d[2]), "+f"(d[3])
        : "r"(a[0]), "r"(a[1]), "r"(a[2]), "r"(a[3]), "r"(b0), "r"(b1));
}

// ---------------------------------------------------------------------------
// Kernel 0: transpose + hi/lo split of the two weight matrices
// ---------------------------------------------------------------------------
__global__ __launch_bounds__(256) void k_split_w(
    const float* __restrict__ wqkv, const float* __restrict__ wout,
    __nv_bfloat16* __restrict__ qT_hi, __nv_bfloat16* __restrict__ qT_lo,
    __nv_bfloat16* __restrict__ oT_hi, __nv_bfloat16* __restrict__ oT_lo)
{
    int e = blockIdx.x * 256 + threadIdx.x;
    if (e < QKVDIM * CDIM) {
        int n = e >> 8, k = e & 255;
        __nv_bfloat16 h, l;
        split_bf16(wqkv[k * QKVDIM + n], h, l);
        qT_hi[e] = h; qT_lo[e] = l;
    } else {
        int e2 = e - QKVDIM * CDIM;
        if (e2 < CDIM * CDIM) {
            int n = e2 >> 8, k = e2 & 255;
            __nv_bfloat16 h, l;
            split_bf16(wout[k * CDIM + n], h, l);
            oT_hi[e2] = h; oT_lo[e2] = l;
        }
    }
}

// ---------------------------------------------------------------------------
// Kernel 1: gather patches + LayerNorm x2, emit hi/lo bf16 planes
// ---------------------------------------------------------------------------
__global__ __launch_bounds__(256) void k_gather_ln(
    const float* __restrict__ x,
    const float* __restrict__ g1, const float* __restrict__ b1,
    const float* __restrict__ g2, const float* __restrict__ b2,
    __nv_bfloat16* __restrict__ hhi, __nv_bfloat16* __restrict__ hlo)
{
    int warp = threadIdx.x >> 5, lane = threadIdx.x & 31;
    int row = blockIdx.x * 8 + warp;          // 0..115199
    int p = row >> 6, t = row & 63;
    int b = p / 225, l = p - b * 225;
    int ph = l / 15, pw = l - ph * 15;
    int gr = ph * 4 + (t >> 3);
    int gc = pw * 4 + (t & 7);
    const float* xr = x + (((size_t)(b * 64 + gr)) * 64 + gc) * 256;

    float v[8];
    float s = 0.f;
#pragma unroll
    for (int i = 0; i < 8; i++) { v[i] = xr[lane + i * 32]; s += v[i]; }
    s = warp_sum(s);
    float mean = s * (1.f / 256.f);
    float vs = 0.f;
#pragma unroll
    for (int i = 0; i < 8; i++) { v[i] -= mean; vs += v[i] * v[i]; }
    vs = warp_sum(vs);
    float inv = rsqrtf(vs * (1.f / 256.f) + 1e-5f);

    float s2 = 0.f;
#pragma unroll
    for (int i = 0; i < 8; i++) {
        v[i] = v[i] * inv * g1[lane + i * 32] + b1[lane + i * 32];
        s2 += v[i];
    }
    s2 = warp_sum(s2);
    float mean2 = s2 * (1.f / 256.f);
    float vs2 = 0.f;
#pragma unroll
    for (int i = 0; i < 8; i++) { v[i] -= mean2; vs2 += v[i] * v[i]; }
    vs2 = warp_sum(vs2);
    float inv2 = rsqrtf(vs2 * (1.f / 256.f) + 1e-5f);

    size_t base = (size_t)row * 256;
#pragma unroll
    for (int i = 0; i < 8; i++) {
        float val = v[i] * inv2 * g2[lane + i * 32] + b2[lane + i * 32];
        __nv_bfloat16 h, lo;
        split_bf16(val, h, lo);
        hhi[base + lane + i * 32] = h;
        hlo[base + lane + i * 32] = lo;
    }
}

// ---------------------------------------------------------------------------
// Tensor-core GEMM via mma.sync (sm_80+ PTX, runs on Blackwell HMMA pipe):
//   C[M,Ntot] = (Ahi+Alo)[M,256] @ (Bhi+Blo)[Ntot,256]^T  (+bias)
// 128x128x32 CTA tile, 8 warps (2x4), warp tile 64x32, split-bf16 3 products.
// smem rows padded to 40 bf16 (80B) => conflict-free ldmatrix.
// ---------------------------------------------------------------------------
#define ASTRIDE 40   // bf16 elements per smem row (32 data + 8 pad)

__global__ __launch_bounds__(256, 2) void k_mma_gemm(
    const __nv_bfloat16* __restrict__ Ahi, const __nv_bfloat16* __restrict__ Alo,
    const __nv_bfloat16* __restrict__ Bhi, const __nv_bfloat16* __restrict__ Blo,
    const float* __restrict__ bias, float* __restrict__ C, int ldc)
{
    __shared__ __align__(16) __nv_bfloat16 sm[4 * 128 * ASTRIDE];  // 40 KB
    __nv_bfloat16* sAh = sm;
    __nv_bfloat16* sAl = sm + 128 * ASTRIDE;
    __nv_bfloat16* sBh = sm + 2 * 128 * ASTRIDE;
    __nv_bfloat16* sBl = sm + 3 * 128 * ASTRIDE;

    int tid  = threadIdx.x;
    int lane = tid & 31, wid = tid >> 5;
    int wm = wid >> 2, wn = wid & 3;          // warp grid 2x4
    int bm = blockIdx.y * 128, bn = blockIdx.x * 128;

    float acc[4][4][4];
#pragma unroll
    for (int i = 0; i < 4; i++)
#pragma unroll
        for (int j = 0; j < 4; j++)
#pragma unroll
            for (int q = 0; q < 4; q++) acc[i][j][q] = 0.f;

    // ldmatrix base addresses (per-thread row assignments)
    // A blocks: t0-7:(m0-7,k0-7) t8-15:(m8-15,k0-7) t16-23:(m0-7,k8-15) t24-31:(m8-15,k8-15)
    int a_row = wm * 64 + (lane & 15);
    int a_kof = (lane >> 4) << 3;
    // B blocks (two n-tiles per x4): t0-7:(n0-7,k0) t8-15:(n0-7,k8) t16-23:(n8-15,k0) t24-31:(n8-15,k8)
    int b_row = wn * 32 + ((lane >> 4) << 3) + (lane & 7);
    int b_kof = ((lane >> 3) & 1) << 3;

    for (int kt = 0; kt < 8; kt++) {
        if (kt) __syncthreads();
        // Global -> smem: per plane 128 rows x 4 segs of 16B
#pragma unroll
        for (int h = 0; h < 2; h++) {
            int v = tid + h * 256;
            int r = v >> 2, s = v & 3;
            size_t ga = (size_t)(bm + r) * 256 + kt * 32 + s * 8;
            size_t gb = (size_t)(bn + r) * 256 + kt * 32 + s * 8;
            int so = r * ASTRIDE + s * 8;
            *(uint4*)(sAh + so) = *(const uint4*)(Ahi + ga);
            *(uint4*)(sAl + so) = *(const uint4*)(Alo + ga);
            *(uint4*)(sBh + so) = *(const uint4*)(Bhi + gb);
            *(uint4*)(sBl + so) = *(const uint4*)(Blo + gb);
        }
        __syncthreads();

#pragma unroll
        for (int ks = 0; ks < 2; ks++) {
            uint32_t af[4][4], bf[2][4];
            int kk = ks * 16;

            // ah fragments
#pragma unroll
            for (int i = 0; i < 4; i++)
                ldsm_x4(smem_to_u32(sAh + (a_row + i * 16) * ASTRIDE + kk + a_kof),
                        af[i][0], af[i][1], af[i][2], af[i][3]);
            // bh fragments
#pragma unroll
            for (int jj = 0; jj < 2; jj++)
                ldsm_x4(smem_to_u32(sBh + (b_row + jj * 16) * ASTRIDE + kk + b_kof),
                        bf[jj][0], bf[jj][1], bf[jj][2], bf[jj][3]);
            // ah * bh
#pragma unroll
            for (int i = 0; i < 4; i++)
#pragma unroll
                for (int j = 0; j < 4; j++)
                    mma_bf16(acc[i][j], af[i], bf[j >> 1][(j & 1) * 2], bf[j >> 1][(j & 1) * 2 + 1]);
            // bl fragments (overwrite bh)
#pragma unroll
            for (int jj = 0; jj < 2; jj++)
                ldsm_x4(smem_to_u32(sBl + (b_row + jj * 16) * ASTRIDE + kk + b_kof),
                        bf[jj][0], bf[jj][1], bf[jj][2], bf[jj][3]);
            // ah * bl
#pragma unroll
            for (int i = 0; i < 4; i++)
#pragma unroll
                for (int j = 0; j < 4; j++)
                    mma_bf16(acc[i][j], af[i], bf[j >> 1][(j & 1) * 2], bf[j >> 1][(j & 1) * 2 + 1]);
            // al fragments (overwrite ah), reload bh
#pragma unroll
            for (int i = 0; i < 4; i++)
                ldsm_x4(smem_to_u32(sAl + (a_row + i * 16) * ASTRIDE + kk + a_kof),
                        af[i][0], af[i][1], af[i][2], af[i][3]);
#pragma unroll
            for (int jj = 0; jj < 2; jj++)
                ldsm_x4(smem_to_u32(sBh + (b_row + jj * 16) * ASTRIDE + kk + b_kof),
                        bf[jj][0], bf[jj][1], bf[jj][2], bf[jj][3]);
            // al * bh
#pragma unroll
            for (int i = 0; i < 4; i++)
#pragma unroll
                for (int j = 0; j < 4; j++)
                    mma_bf16(acc[i][j], af[i], bf[j >> 1][(j & 1) * 2], bf[j >> 1][(j & 1) * 2 + 1]);
        }
    }

    // Epilogue: c fragment = {(r,c),(r,c+1),(r+8,c),(r+8,c+1)}, r=lane>>2, c=(lane&3)*2
    int er = lane >> 2, ec = (lane & 3) * 2;
#pragma unroll
    for (int i = 0; i < 4; i++) {
#pragma unroll
        for (int j = 0; j < 4; j++) {
            int row0 = bm + wm * 64 + i * 16 + er;
            int col  = bn + wn * 32 + j * 8 + ec;
            float bx = 0.f, by = 0.f;
            if (bias) { bx = bias[col]; by = bias[col + 1]; }
            float2 v0 = make_float2(acc[i][j][0] + bx, acc[i][j][1] + by);
            float2 v1 = make_float2(acc[i][j][2] + bx, acc[i][j][3] + by);
            *(float2*)(C + (size_t)row0 * ldc + col)       = v0;
            *(float2*)(C + (size_t)(row0 + 8) * ldc + col) = v1;
        }
    }
}

// ---------------------------------------------------------------------------
// Kernel 3: per-patch multi-head attention (online softmax), fp32.
// One CTA per patch, 512 threads = (head, query token). Emits hi/lo planes.
// ---------------------------------------------------------------------------
#define ATTN_STRIDE 260
#define ATTN_SMEM   (3 * 64 * ATTN_STRIDE * 4)

__global__ __launch_bounds__(512) void k_attn(
    const float* __restrict__ qkv,
    __nv_bfloat16* __restrict__ ohi, __nv_bfloat16* __restrict__ olo)
{
    extern __shared__ float sm[];
    float* Qs = sm;
    float* Ks = sm + 64 * ATTN_STRIDE;
    float* Vs = sm + 2 * 64 * ATTN_STRIDE;

    int p = blockIdx.x;
    int tid = threadIdx.x;
    const float* src = qkv + (size_t)p * 64 * 768;

    for (int idx = tid; idx < 64 * 768; idx += 512) {
        int row = idx / 768;
        int col = idx - row * 768;
        int sec = col >> 8;
        int cc  = col & 255;
        sm[sec * (64 * ATTN_STRIDE) + row * ATTN_STRIDE + cc] = src[idx];
    }
    __syncthreads();

    int h = tid >> 6, t = tid & 63;
    const int hb = h * 32;

    float q[32];
    {
        const float* qr = Qs + t * ATTN_STRIDE + hb;
#pragma unroll
        for (int d = 0; d < 32; d++)
            q[d] = qr[d] * 0.17677669529663687f;
    }

    float m = -1e30f, ssum = 0.f;
    float o[32];
#pragma unroll
    for (int d = 0; d < 32; d++) o[d] = 0.f;

    for (int j = 0; j < 64; j++) {
        const float4* kr = (const float4*)(Ks + j * ATTN_STRIDE + hb);
        float s = 0.f;
#pragma unroll
        for (int d4 = 0; d4 < 8; d4++) {
            float4 k4 = kr[d4];
            s += q[d4 * 4 + 0] * k4.x + q[d4 * 4 + 1] * k4.y
               + q[d4 * 4 + 2] * k4.z + q[d4 * 4 + 3] * k4.w;
        }
        float mn   = fmaxf(m, s);
        float corr = __expf(m - mn);
        float e    = __expf(s - mn);
        ssum = ssum * corr + e;
        const float4* vr = (const float4*)(Vs + j * ATTN_STRIDE + hb);
#pragma unroll
        for (int d4 = 0; d4 < 8; d4++) {
            float4 v4 = vr[d4];
            o[d4 * 4 + 0] = o[d4 * 4 + 0] * corr + e * v4.x;
            o[d4 * 4 + 1] = o[d4 * 4 + 1] * corr + e * v4.y;
            o[d4 * 4 + 2] = o[d4 * 4 + 2] * corr + e * v4.z;
            o[d4 * 4 + 3] = o[d4 * 4 + 3] * corr + e * v4.w;
        }
        m = mn;
    }

    float invs = 1.f / ssum;
    __syncthreads();
    {
        float* qr = Qs + t * ATTN_STRIDE + hb;
#pragma unroll
        for (int d = 0; d < 32; d++) qr[d] = o[d] * invs;
    }
    __syncthreads();

    size_t dbase = (size_t)p * 64 * 256;
    for (int idx = tid; idx < 64 * 256; idx += 512) {
        int row = idx >> 8, cc = idx & 255;
        float val = Qs[row * ATTN_STRIDE + cc];
        __nv_bfloat16 hv, lv;
        split_bf16(val, hv, lv);
        ohi[dbase + idx] = hv;
        olo[dbase + idx] = lv;
    }
}

// ---------------------------------------------------------------------------
// Kernel 5: deterministic overlap-gather + count normalization.
// ---------------------------------------------------------------------------
__global__ __launch_bounds__(256) void k_scatter(
    const float* __restrict__ y, float* __restrict__ out)
{
    int pix = blockIdx.x;
    int ch  = threadIdx.x;
    int b = pix >> 12;
    int r = (pix >> 6) & 63;
    int c = pix & 63;

    int ph_lo = max(0, (r - 4) >> 2);
    int ph_hi = min(14, r >> 2);
    int pw_lo = max(0, (c - 4) >> 2);
    int pw_hi = min(14, c >> 2);

    float acc = 0.f;
    for (int ph = ph_lo; ph <= ph_hi; ph++) {
        for (int pw = pw_lo; pw <= pw_hi; pw++) {
            int p = b * 225 + ph * 15 + pw;
            int t = (r - ph * 4) * 8 + (c - pw * 4);
            acc += y[((size_t)p * 64 + t) * 256 + ch];
        }
    }
    float cnt = (float)((ph_hi - ph_lo + 1) * (pw_hi - pw_lo + 1));
    out[(size_t)pix * 256 + ch] = acc * (1.f / cnt);
}

// ---------------------------------------------------------------------------
// Entry point
// ---------------------------------------------------------------------------
extern "C" void kernel_launch(void* const* d_in, const int* in_sizes, int n_in,
                              void* d_out, int out_size)
{
    const float* x    = (const float*)d_in[0];
    const float* g1   = (const float*)d_in[1];
    const float* b1   = (const float*)d_in[2];
    const float* g2   = (const float*)d_in[3];
    const float* b2   = (const float*)d_in[4];
    const float* wqkv = (const float*)d_in[5];
    const float* wout = (const float*)d_in[6];
    const float* bout = (const float*)d_in[7];
    float* out = (float*)d_out;

    float* bigbuf;
    __nv_bfloat16 *phi, *plo, *wqh, *wql, *woh, *wol;
    cudaGetSymbolAddress((void**)&bigbuf, g_big);
    cudaGetSymbolAddress((void**)&phi, g_phi);
    cudaGetSymbolAddress((void**)&plo, g_plo);
    cudaGetSymbolAddress((void**)&wqh, g_wqT_hi);
    cudaGetSymbolAddress((void**)&wql, g_wqT_lo);
    cudaGetSymbolAddress((void**)&woh, g_woT_hi);
    cudaGetSymbolAddress((void**)&wol, g_woT_lo);

    float* qkvbuf = bigbuf;   // GEMM1 out / attn in
    float* ybuf   = bigbuf;   // GEMM2 out / scatter in (qkv dead by then)

    cudaFuncSetAttribute(k_attn, cudaFuncAttributeMaxDynamicSharedMemorySize, ATTN_SMEM);

    k_split_w<<<(QKVDIM * CDIM + CDIM * CDIM + 255) / 256, 256>>>(wqkv, wout, wqh, wql, woh, wol);
    k_gather_ln<<<MROWS / 8, 256>>>(x, g1, b1, g2, b2, phi, plo);
    k_mma_gemm<<<dim3(QKVDIM / 128, MROWS / 128), 256>>>(
        phi, plo, wqh, wql, nullptr, qkvbuf, QKVDIM);
    k_attn<<<NPATCH, 512, ATTN_SMEM>>>(qkvbuf, phi, plo);   // overwrite h planes with o planes
    k_mma_gemm<<<dim3(CDIM / 128, MROWS / 128), 256>>>(
        phi, plo, woh, wol, bout, ybuf, CDIM);
    k_scatter<<<8 * 64 * 64, 256>>>(ybuf, out);
}

// round 6
// speedup vs baseline: 2.1302x; 1.3166x over previous
#include <cuda_runtime.h>
#include <cuda_bf16.h>
#include <cstdint>
#include <math.h>

// ---------------------------------------------------------------------------
// Problem constants
// ---------------------------------------------------------------------------
#define NPATCH 1800            // B(8) * L(225)
#define NTOK   64              // k*k
#define CDIM   256
#define QKVDIM 768
#define MROWS  (NPATCH * NTOK) // 115200
#define SCALE_ATT 0.17677669529663687f

// ---------------------------------------------------------------------------
// Global scratch.
//  g_qh/g_ql : qkv hi/lo bf16 planes (GEMM1 out / attn in). g_qh is re-used
//              (reinterpreted as float*) as y, the GEMM2 fp32 output.
//  g_phi/g_plo : h hi/lo (LN out / GEMM1 A), then o hi/lo (attn out / GEMM2 A)
// ---------------------------------------------------------------------------
__device__ __nv_bfloat16  g_qh[(size_t)MROWS * QKVDIM];   // 177 MB
__device__ __nv_bfloat16  g_ql[(size_t)MROWS * QKVDIM];   // 177 MB
__device__ __nv_bfloat16  g_phi[(size_t)MROWS * CDIM];    // 59 MB
__device__ __nv_bfloat16  g_plo[(size_t)MROWS * CDIM];    // 59 MB
__device__ __nv_bfloat16  g_wqT_hi[QKVDIM * CDIM];
__device__ __nv_bfloat16  g_wqT_lo[QKVDIM * CDIM];
__device__ __nv_bfloat16  g_woT_hi[CDIM * CDIM];
__device__ __nv_bfloat16  g_woT_lo[CDIM * CDIM];

// ---------------------------------------------------------------------------
// Helpers
// ---------------------------------------------------------------------------
__device__ __forceinline__ uint32_t smem_to_u32(const void* p) {
    uint32_t a;
    asm("{ .reg .u64 t; cvta.to.shared.u64 t, %1; cvt.u32.u64 %0, t; }"
        : "=r"(a) : "l"(p));
    return a;
}
__device__ __forceinline__ float warp_sum(float v) {
#pragma unroll
    for (int o = 16; o; o >>= 1) v += __shfl_xor_sync(0xffffffffu, v, o);
    return v;
}
__device__ __forceinline__ void split_bf16(float v, __nv_bfloat16& hi, __nv_bfloat16& lo) {
    hi = __float2bfloat16(v);
    lo = __float2bfloat16(v - __bfloat162float(hi));
}
__device__ __forceinline__ void ldsm_x4(uint32_t addr, uint32_t& r0, uint32_t& r1,
                                        uint32_t& r2, uint32_t& r3) {
    asm volatile("ldmatrix.sync.aligned.m8n8.x4.shared.b16 {%0,%1,%2,%3}, [%4];"
                 : "=r"(r0), "=r"(r1), "=r"(r2), "=r"(r3) : "r"(addr));
}
__device__ __forceinline__ void ldsm_x4_t(uint32_t addr, uint32_t* r) {
    asm volatile("ldmatrix.sync.aligned.m8n8.x4.trans.shared.b16 {%0,%1,%2,%3}, [%4];"
                 : "=r"(r[0]), "=r"(r[1]), "=r"(r[2]), "=r"(r[3]) : "r"(addr));
}
__device__ __forceinline__ void mma_bf16(float* d, const uint32_t* a,
                                         uint32_t b0, uint32_t b1) {
    asm volatile(
        "mma.sync.aligned.m16n8k16.row.col.f32.bf16.bf16.f32 "
        "{%0,%1,%2,%3}, {%4,%5,%6,%7}, {%8,%9}, {%0,%1,%2,%3};"
        : "+f"(d[0]), "+f"(d[1]), "+f"(d[2]), "+f"(d[3])
        : "r"(a[0]), "r"(a[1]), "r"(a[2]), "r"(a[3]), "r"(b0), "r"(b1));
}
// pack (lo_elem, hi_elem) floats into bf16x2 reg; residuals returned
__device__ __forceinline__ uint32_t pack_split(float c0, float c1, float& r0, float& r1) {
    __nv_bfloat162 t = __floats2bfloat162_rn(c0, c1);  // .x = c0 (low half)
    r0 = c0 - __bfloat162float(t.x);
    r1 = c1 - __bfloat162float(t.y);
    return *reinterpret_cast<uint32_t*>(&t);
}
__device__ __forceinline__ uint32_t pack2(float c0, float c1) {
    __nv_bfloat162 t = __floats2bfloat162_rn(c0, c1);
    return *reinterpret_cast<uint32_t*>(&t);
}

// ---------------------------------------------------------------------------
// Kernel 0: transpose + hi/lo split of the two weight matrices
// ---------------------------------------------------------------------------
__global__ __launch_bounds__(256) void k_split_w(
    const float* __restrict__ wqkv, const float* __restrict__ wout,
    __nv_bfloat16* __restrict__ qT_hi, __nv_bfloat16* __restrict__ qT_lo,
    __nv_bfloat16* __restrict__ oT_hi, __nv_bfloat16* __restrict__ oT_lo)
{
    int e = blockIdx.x * 256 + threadIdx.x;
    if (e < QKVDIM * CDIM) {
        int n = e >> 8, k = e & 255;
        __nv_bfloat16 h, l;
        split_bf16(wqkv[k * QKVDIM + n], h, l);
        qT_hi[e] = h; qT_lo[e] = l;
    } else {
        int e2 = e - QKVDIM * CDIM;
        if (e2 < CDIM * CDIM) {
            int n = e2 >> 8, k = e2 & 255;
            __nv_bfloat16 h, l;
            split_bf16(wout[k * CDIM + n], h, l);
            oT_hi[e2] = h; oT_lo[e2] = l;
        }
    }
}

// ---------------------------------------------------------------------------
// Kernel 1: gather patches + LayerNorm x2, emit hi/lo bf16 planes
// ---------------------------------------------------------------------------
__global__ __launch_bounds__(256) void k_gather_ln(
    const float* __restrict__ x,
    const float* __restrict__ g1, const float* __restrict__ b1,
    const float* __restrict__ g2, const float* __restrict__ b2,
    __nv_bfloat16* __restrict__ hhi, __nv_bfloat16* __restrict__ hlo)
{
    int warp = threadIdx.x >> 5, lane = threadIdx.x & 31;
    int row = blockIdx.x * 8 + warp;
    int p = row >> 6, t = row & 63;
    int b = p / 225, l = p - b * 225;
    int ph = l / 15, pw = l - ph * 15;
    int gr = ph * 4 + (t >> 3);
    int gc = pw * 4 + (t & 7);
    const float* xr = x + (((size_t)(b * 64 + gr)) * 64 + gc) * 256;

    float v[8];
    float s = 0.f;
#pragma unroll
    for (int i = 0; i < 8; i++) { v[i] = xr[lane + i * 32]; s += v[i]; }
    s = warp_sum(s);
    float mean = s * (1.f / 256.f);
    float vs = 0.f;
#pragma unroll
    for (int i = 0; i < 8; i++) { v[i] -= mean; vs += v[i] * v[i]; }
    vs = warp_sum(vs);
    float inv = rsqrtf(vs * (1.f / 256.f) + 1e-5f);

    float s2 = 0.f;
#pragma unroll
    for (int i = 0; i < 8; i++) {
        v[i] = v[i] * inv * g1[lane + i * 32] + b1[lane + i * 32];
        s2 += v[i];
    }
    s2 = warp_sum(s2);
    float mean2 = s2 * (1.f / 256.f);
    float vs2 = 0.f;
#pragma unroll
    for (int i = 0; i < 8; i++) { v[i] -= mean2; vs2 += v[i] * v[i]; }
    vs2 = warp_sum(vs2);
    float inv2 = rsqrtf(vs2 * (1.f / 256.f) + 1e-5f);

    size_t base = (size_t)row * 256;
#pragma unroll
    for (int i = 0; i < 8; i++) {
        float val = v[i] * inv2 * g2[lane + i * 32] + b2[lane + i * 32];
        __nv_bfloat16 h, lo;
        split_bf16(val, h, lo);
        hhi[base + lane + i * 32] = h;
        hlo[base + lane + i * 32] = lo;
    }
}

// ---------------------------------------------------------------------------
// mma.sync GEMM: C = (Ahi+Alo)[M,256] @ (Bhi+Blo)[N,256]^T
// Output either fp32 (+bias) via Cf, or hi/lo split bf16 planes via Ch/Cl.
// ---------------------------------------------------------------------------
#define ASTRIDE 40

__global__ __launch_bounds__(256, 2) void k_mma_gemm(
    const __nv_bfloat16* __restrict__ Ahi, const __nv_bfloat16* __restrict__ Alo,
    const __nv_bfloat16* __restrict__ Bhi, const __nv_bfloat16* __restrict__ Blo,
    const float* __restrict__ bias, float* __restrict__ Cf,
    __nv_bfloat16* __restrict__ Ch, __nv_bfloat16* __restrict__ Cl, int ldc)
{
    __shared__ __align__(16) __nv_bfloat16 sm[4 * 128 * ASTRIDE];
    __nv_bfloat16* sAh = sm;
    __nv_bfloat16* sAl = sm + 128 * ASTRIDE;
    __nv_bfloat16* sBh = sm + 2 * 128 * ASTRIDE;
    __nv_bfloat16* sBl = sm + 3 * 128 * ASTRIDE;

    int tid  = threadIdx.x;
    int lane = tid & 31, wid = tid >> 5;
    int wm = wid >> 2, wn = wid & 3;
    int bm = blockIdx.y * 128, bn = blockIdx.x * 128;

    float acc[4][4][4];
#pragma unroll
    for (int i = 0; i < 4; i++)
#pragma unroll
        for (int j = 0; j < 4; j++)
#pragma unroll
            for (int q = 0; q < 4; q++) acc[i][j][q] = 0.f;

    int a_row = wm * 64 + (lane & 15);
    int a_kof = (lane >> 4) << 3;
    int b_row = wn * 32 + ((lane >> 4) << 3) + (lane & 7);
    int b_kof = ((lane >> 3) & 1) << 3;

    for (int kt = 0; kt < 8; kt++) {
        if (kt) __syncthreads();
#pragma unroll
        for (int h = 0; h < 2; h++) {
            int v = tid + h * 256;
            int r = v >> 2, s = v & 3;
            size_t ga = (size_t)(bm + r) * 256 + kt * 32 + s * 8;
            size_t gb = (size_t)(bn + r) * 256 + kt * 32 + s * 8;
            int so = r * ASTRIDE + s * 8;
            *(uint4*)(sAh + so) = *(const uint4*)(Ahi + ga);
            *(uint4*)(sAl + so) = *(const uint4*)(Alo + ga);
            *(uint4*)(sBh + so) = *(const uint4*)(Bhi + gb);
            *(uint4*)(sBl + so) = *(const uint4*)(Blo + gb);
        }
        __syncthreads();

#pragma unroll
        for (int ks = 0; ks < 2; ks++) {
            uint32_t af[4][4], bf[2][4];
            int kk = ks * 16;
#pragma unroll
            for (int i = 0; i < 4; i++)
                ldsm_x4(smem_to_u32(sAh + (a_row + i * 16) * ASTRIDE + kk + a_kof),
                        af[i][0], af[i][1], af[i][2], af[i][3]);
#pragma unroll
            for (int jj = 0; jj < 2; jj++)
                ldsm_x4(smem_to_u32(sBh + (b_row + jj * 16) * ASTRIDE + kk + b_kof),
                        bf[jj][0], bf[jj][1], bf[jj][2], bf[jj][3]);
#pragma unroll
            for (int i = 0; i < 4; i++)
#pragma unroll
                for (int j = 0; j < 4; j++)
                    mma_bf16(acc[i][j], af[i], bf[j >> 1][(j & 1) * 2], bf[j >> 1][(j & 1) * 2 + 1]);
#pragma unroll
            for (int jj = 0; jj < 2; jj++)
                ldsm_x4(smem_to_u32(sBl + (b_row + jj * 16) * ASTRIDE + kk + b_kof),
                        bf[jj][0], bf[jj][1], bf[jj][2], bf[jj][3]);
#pragma unroll
            for (int i = 0; i < 4; i++)
#pragma unroll
                for (int j = 0; j < 4; j++)
                    mma_bf16(acc[i][j], af[i], bf[j >> 1][(j & 1) * 2], bf[j >> 1][(j & 1) * 2 + 1]);
#pragma unroll
            for (int i = 0; i < 4; i++)
                ldsm_x4(smem_to_u32(sAl + (a_row + i * 16) * ASTRIDE + kk + a_kof),
                        af[i][0], af[i][1], af[i][2], af[i][3]);
#pragma unroll
            for (int jj = 0; jj < 2; jj++)
                ldsm_x4(smem_to_u32(sBh + (b_row + jj * 16) * ASTRIDE + kk + b_kof),
                        bf[jj][0], bf[jj][1], bf[jj][2], bf[jj][3]);
#pragma unroll
            for (int i = 0; i < 4; i++)
#pragma unroll
                for (int j = 0; j < 4; j++)
                    mma_bf16(acc[i][j], af[i], bf[j >> 1][(j & 1) * 2], bf[j >> 1][(j & 1) * 2 + 1]);
        }
    }

    int er = lane >> 2, ec = (lane & 3) * 2;
#pragma unroll
    for (int i = 0; i < 4; i++) {
#pragma unroll
        for (int j = 0; j < 4; j++) {
            int row0 = bm + wm * 64 + i * 16 + er;
            int col  = bn + wn * 32 + j * 8 + ec;
            if (Cf) {
                float bx = 0.f, by = 0.f;
                if (bias) { bx = bias[col]; by = bias[col + 1]; }
                *(float2*)(Cf + (size_t)row0 * ldc + col) =
                    make_float2(acc[i][j][0] + bx, acc[i][j][1] + by);
                *(float2*)(Cf + (size_t)(row0 + 8) * ldc + col) =
                    make_float2(acc[i][j][2] + bx, acc[i][j][3] + by);
            } else {
                float r0, r1;
                uint32_t hi0 = pack_split(acc[i][j][0], acc[i][j][1], r0, r1);
                *(uint32_t*)(Ch + (size_t)row0 * ldc + col) = hi0;
                *(uint32_t*)(Cl + (size_t)row0 * ldc + col) = pack2(r0, r1);
                uint32_t hi1 = pack_split(acc[i][j][2], acc[i][j][3], r0, r1);
                *(uint32_t*)(Ch + (size_t)(row0 + 8) * ldc + col) = hi1;
                *(uint32_t*)(Cl + (size_t)(row0 + 8) * ldc + col) = pack2(r0, r1);
            }
        }
    }
}

// ---------------------------------------------------------------------------
// Kernel 3: FA2-style per-patch attention on tensor cores.
// 1 CTA = 1 patch, 8 warps = 1 warp per head.
// smem: 6 planes (Q,K,V x hi,lo), 64 x 264 bf16 each, stride 528B (conflict-free).
// ---------------------------------------------------------------------------
#define QS  264
#define PLN (64 * QS)
#define ATTN_SM_BYTES (6 * PLN * 2)   // 202752 B

__global__ __launch_bounds__(256) void k_attn_mma(
    const __nv_bfloat16* __restrict__ qkvh, const __nv_bfloat16* __restrict__ qkvl,
    __nv_bfloat16* __restrict__ ohi, __nv_bfloat16* __restrict__ olo)
{
    extern __shared__ __nv_bfloat16 sm[];
    // plane order: Qh, Kh, Vh, Ql, Kl, Vl
    int p = blockIdx.x, tid = threadIdx.x;
    {
        const uint4* sh = (const uint4*)(qkvh + (size_t)p * 64 * 768);
        const uint4* sl = (const uint4*)(qkvl + (size_t)p * 64 * 768);
#pragma unroll 4
        for (int i = tid; i < 6144; i += 256) {
            int row = i / 96, cb = (i - row * 96) * 8;  // bf16 col in 0..767
            int sec = cb >> 8, cc = cb & 255;
            int d = sec * PLN + row * QS + cc;
            *(uint4*)(sm + d)           = sh[i];
            *(uint4*)(sm + 3 * PLN + d) = sl[i];
        }
    }
    __syncthreads();

    int lane = tid & 31, h = tid >> 5;
    int hb = h * 32;
    int gr = lane >> 2, gc = (lane & 3) * 2;

    uint32_t base = smem_to_u32(sm);
    // ldmatrix lane-address components (validated layouts from the GEMM kernel)
    int a_r = lane & 15;                          // + qb*16        (A: Q rows)
    int a_c = (lane >> 4) << 3;                   // + kk*16 + hb   (A: k cols)
    int b_r = ((lane >> 4) << 3) + (lane & 7);    // + jp*16        (B: K rows)
    int b_c = ((lane >> 3) & 1) << 3;             // + kk*16 + hb
    int v_r = (((lane >> 3) & 1) << 3) + (lane & 7); // + kk*16     (B^T: V token rows)
    int v_c = (lane >> 4) << 3;                   // + dp*16 + hb

    for (int qb = 0; qb < 4; qb++) {
        float s[8][4];
#pragma unroll
        for (int j = 0; j < 8; j++)
#pragma unroll
            for (int q = 0; q < 4; q++) s[j][q] = 0.f;

        // ---- S = (Qh+Ql) @ Kh^T ----
#pragma unroll
        for (int kk = 0; kk < 2; kk++) {
            uint32_t aH[4], aL[4];
            uint32_t qoff = (uint32_t)((qb * 16 + a_r) * QS + hb + kk * 16 + a_c) * 2;
            ldsm_x4(base + 0 * PLN * 2 + qoff, aH[0], aH[1], aH[2], aH[3]);
            ldsm_x4(base + 3 * PLN * 2 + qoff, aL[0], aL[1], aL[2], aL[3]);
#pragma unroll
            for (int jp = 0; jp < 4; jp++) {
                uint32_t kf[4];
                uint32_t koff = (uint32_t)((jp * 16 + b_r) * QS + hb + kk * 16 + b_c) * 2;
                ldsm_x4(base + 1 * PLN * 2 + koff, kf[0], kf[1], kf[2], kf[3]);
                mma_bf16(s[2 * jp],     aH, kf[0], kf[1]);
                mma_bf16(s[2 * jp + 1], aH, kf[2], kf[3]);
                mma_bf16(s[2 * jp],     aL, kf[0], kf[1]);
                mma_bf16(s[2 * jp + 1], aL, kf[2], kf[3]);
            }
        }

        // ---- softmax (full row in registers + quad shuffle) ----
        float mx0 = -1e30f, mx1 = -1e30f;
#pragma unroll
        for (int j = 0; j < 8; j++) {
#pragma unroll
            for (int q = 0; q < 4; q++) s[j][q] *= SCALE_ATT;
            mx0 = fmaxf(mx0, fmaxf(s[j][0], s[j][1]));
            mx1 = fmaxf(mx1, fmaxf(s[j][2], s[j][3]));
        }
        mx0 = fmaxf(mx0, __shfl_xor_sync(0xffffffffu, mx0, 1));
        mx0 = fmaxf(mx0, __shfl_xor_sync(0xffffffffu, mx0, 2));
        mx1 = fmaxf(mx1, __shfl_xor_sync(0xffffffffu, mx1, 1));
        mx1 = fmaxf(mx1, __shfl_xor_sync(0xffffffffu, mx1, 2));
        float sum0 = 0.f, sum1 = 0.f;
#pragma unroll
        for (int j = 0; j < 8; j++) {
            s[j][0] = __expf(s[j][0] - mx0);
            s[j][1] = __expf(s[j][1] - mx0);
            s[j][2] = __expf(s[j][2] - mx1);
            s[j][3] = __expf(s[j][3] - mx1);
            sum0 += s[j][0] + s[j][1];
            sum1 += s[j][2] + s[j][3];
        }
        sum0 += __shfl_xor_sync(0xffffffffu, sum0, 1);
        sum0 += __shfl_xor_sync(0xffffffffu, sum0, 2);
        sum1 += __shfl_xor_sync(0xffffffffu, sum1, 1);
        sum1 += __shfl_xor_sync(0xffffffffu, sum1, 2);

        // ---- O = P @ V (3 split products) ----
        float o[4][4];
#pragma unroll
        for (int t = 0; t < 4; t++)
#pragma unroll
            for (int q = 0; q < 4; q++) o[t][q] = 0.f;

#pragma unroll
        for (int kk = 0; kk < 4; kk++) {
            uint32_t ph[4], pl[4];
            float r0, r1;
            ph[0] = pack_split(s[2 * kk][0],     s[2 * kk][1],     r0, r1); pl[0] = pack2(r0, r1);
            ph[1] = pack_split(s[2 * kk][2],     s[2 * kk][3],     r0, r1); pl[1] = pack2(r0, r1);
            ph[2] = pack_split(s[2 * kk + 1][0], s[2 * kk + 1][1], r0, r1); pl[2] = pack2(r0, r1);
            ph[3] = pack_split(s[2 * kk + 1][2], s[2 * kk + 1][3], r0, r1); pl[3] = pack2(r0, r1);

            uint32_t vh[8], vl[8];
            uint32_t voff0 = (uint32_t)((kk * 16 + v_r) * QS + hb + v_c) * 2;
            uint32_t voff1 = (uint32_t)((kk * 16 + v_r) * QS + hb + 16 + v_c) * 2;
            ldsm_x4_t(base + 2 * PLN * 2 + voff0, vh);
            ldsm_x4_t(base + 2 * PLN * 2 + voff1, vh + 4);
            ldsm_x4_t(base + 5 * PLN * 2 + voff0, vl);
            ldsm_x4_t(base + 5 * PLN * 2 + voff1, vl + 4);
#pragma unroll
            for (int t = 0; t < 4; t++) {
                mma_bf16(o[t], ph, vh[2 * t], vh[2 * t + 1]);
                mma_bf16(o[t], ph, vl[2 * t], vl[2 * t + 1]);
                mma_bf16(o[t], pl, vh[2 * t], vh[2 * t + 1]);
            }
        }

        float inv0 = 1.f / sum0, inv1 = 1.f / sum1;
        size_t row0 = (size_t)(p * 64 + qb * 16 + gr) * 256 + hb;
        size_t row1 = row0 + 8 * 256;
#pragma unroll
        for (int t = 0; t < 4; t++) {
            int col = t * 8 + gc;
            float r0, r1;
            uint32_t hi0 = pack_split(o[t][0] * inv0, o[t][1] * inv0, r0, r1);
            *(uint32_t*)(ohi + row0 + col) = hi0;
            *(uint32_t*)(olo + row0 + col) = pack2(r0, r1);
            uint32_t hi1 = pack_split(o[t][2] * inv1, o[t][3] * inv1, r0, r1);
            *(uint32_t*)(ohi + row1 + col) = hi1;
            *(uint32_t*)(olo + row1 + col) = pack2(r0, r1);
        }
    }
}

// ---------------------------------------------------------------------------
// Kernel 5: deterministic overlap-gather + count normalization.
// ---------------------------------------------------------------------------
__global__ __launch_bounds__(256) void k_scatter(
    const float* __restrict__ y, float* __restrict__ out)
{
    int pix = blockIdx.x;
    int ch  = threadIdx.x;
    int b = pix >> 12;
    int r = (pix >> 6) & 63;
    int c = pix & 63;

    int ph_lo = max(0, (r - 4) >> 2);
    int ph_hi = min(14, r >> 2);
    int pw_lo = max(0, (c - 4) >> 2);
    int pw_hi = min(14, c >> 2);

    float acc = 0.f;
    for (int ph = ph_lo; ph <= ph_hi; ph++) {
        for (int pw = pw_lo; pw <= pw_hi; pw++) {
            int p = b * 225 + ph * 15 + pw;
            int t = (r - ph * 4) * 8 + (c - pw * 4);
            acc += y[((size_t)p * 64 + t) * 256 + ch];
        }
    }
    float cnt = (float)((ph_hi - ph_lo + 1) * (pw_hi - pw_lo + 1));
    out[(size_t)pix * 256 + ch] = acc * (1.f / cnt);
}

// ---------------------------------------------------------------------------
// Entry point
// ---------------------------------------------------------------------------
extern "C" void kernel_launch(void* const* d_in, const int* in_sizes, int n_in,
                              void* d_out, int out_size)
{
    const float* x    = (const float*)d_in[0];
    const float* g1   = (const float*)d_in[1];
    const float* b1   = (const float*)d_in[2];
    const float* g2   = (const float*)d_in[3];
    const float* b2   = (const float*)d_in[4];
    const float* wqkv = (const float*)d_in[5];
    const float* wout = (const float*)d_in[6];
    const float* bout = (const float*)d_in[7];
    float* out = (float*)d_out;

    __nv_bfloat16 *qh, *ql, *phi, *plo, *wqh, *wql, *woh, *wol;
    cudaGetSymbolAddress((void**)&qh,  g_qh);
    cudaGetSymbolAddress((void**)&ql,  g_ql);
    cudaGetSymbolAddress((void**)&phi, g_phi);
    cudaGetSymbolAddress((void**)&plo, g_plo);
    cudaGetSymbolAddress((void**)&wqh, g_wqT_hi);
    cudaGetSymbolAddress((void**)&wql, g_wqT_lo);
    cudaGetSymbolAddress((void**)&woh, g_woT_hi);
    cudaGetSymbolAddress((void**)&wol, g_woT_lo);

    float* ybuf = (float*)qh;   // qkv planes dead after attention

    cudaFuncSetAttribute(k_attn_mma, cudaFuncAttributeMaxDynamicSharedMemorySize,
                         ATTN_SM_BYTES);

    k_split_w<<<(QKVDIM * CDIM + CDIM * CDIM + 255) / 256, 256>>>(
        wqkv, wout, wqh, wql, woh, wol);
    k_gather_ln<<<MROWS / 8, 256>>>(x, g1, b1, g2, b2, phi, plo);
    k_mma_gemm<<<dim3(QKVDIM / 128, MROWS / 128), 256>>>(
        phi, plo, wqh, wql, nullptr, nullptr, qh, ql, QKVDIM);
    k_attn_mma<<<NPATCH, 256, ATTN_SM_BYTES>>>(qh, ql, phi, plo);
    k_mma_gemm<<<dim3(CDIM / 128, MROWS / 128), 256>>>(
        phi, plo, woh, wol, bout, ybuf, nullptr, nullptr, CDIM);
    k_scatter<<<8 * 64 * 64, 256>>>(ybuf, out);
}